// round 2
// baseline (speedup 1.0000x reference)
#include <cuda_runtime.h>
#include <cstdint>

typedef unsigned long long u64;
typedef unsigned int u32;

#define B_ROWS 2048
#define N_TRAIN 100000
#define KDIM 1024
#define NCLS 1000
#define MAXK 200
#define CAP 4096
#define TINV (1.0f / 0.07f)

// 800 MB scratch for the similarity matrix (device global: allocation-free).
__device__ float g_sim[(size_t)B_ROWS * N_TRAIN];

// ---------------------------------------------------------------------------
// Packed f32x2 helpers (Blackwell): 2 fp32 MACs per instruction.
// ---------------------------------------------------------------------------
__device__ __forceinline__ u64 ffma2(u64 a, u64 b, u64 c) {
    u64 d;
    asm("fma.rn.f32x2 %0, %1, %2, %3;" : "=l"(d) : "l"(a), "l"(b), "l"(c));
    return d;
}
__device__ __forceinline__ u64 packf2(float lo, float hi) {
    u64 r;
    asm("mov.b64 %0, {%1, %2};" : "=l"(r) : "f"(lo), "f"(hi));
    return r;
}

// ---------------------------------------------------------------------------
// GEMM: sim[m][n] = sum_d A[m][d] * B[n][d]   (both K-contiguous, "NT")
// 128x128 tile, BK=16, 256 threads, 8x8 per thread, f32x2-packed along n.
// ---------------------------------------------------------------------------
#define BM 128
#define BN 128
#define BK 16
#define TSTRIDE 132   // padded smem row stride (floats), 16B-divisible

__global__ __launch_bounds__(256, 2) void gemm_kernel(
    const float* __restrict__ A, const float* __restrict__ B)
{
    __shared__ float As[BK][TSTRIDE];
    __shared__ float Bs[BK][TSTRIDE];

    const int tid = threadIdx.x;
    const int m_base = blockIdx.y * BM;
    const int n_base = blockIdx.x * BN;

    // tile-load mapping: 128 rows x 16 cols = 512 float4; 2 float4 / thread
    const int lrow = tid >> 2;          // 0..63
    const int lcol = (tid & 3) << 2;    // 0,4,8,12

    // compute mapping: 16x16 thread grid, 8x8 outputs each
    const int ty = tid >> 4, tx = tid & 15;
    const int m0 = ty * 8, n0 = tx * 8;

    u64 acc[8][4];
#pragma unroll
    for (int i = 0; i < 8; i++)
#pragma unroll
        for (int j = 0; j < 4; j++) acc[i][j] = 0ULL;

    const int mA0 = m_base + lrow;      // always < 2048
    const int mA1 = mA0 + 64;
    const int nB0 = n_base + lrow;      // may exceed N_TRAIN on last tile
    const int nB1 = nB0 + 64;

    for (int kt = 0; kt < KDIM; kt += BK) {
        float4 a0 = *(const float4*)(A + (size_t)mA0 * KDIM + kt + lcol);
        float4 a1 = *(const float4*)(A + (size_t)mA1 * KDIM + kt + lcol);
        float4 b0 = make_float4(0.f, 0.f, 0.f, 0.f);
        float4 b1 = make_float4(0.f, 0.f, 0.f, 0.f);
        if (nB0 < N_TRAIN) b0 = *(const float4*)(B + (size_t)nB0 * KDIM + kt + lcol);
        if (nB1 < N_TRAIN) b1 = *(const float4*)(B + (size_t)nB1 * KDIM + kt + lcol);

        __syncthreads();   // previous tile's compute done before overwrite
        As[lcol + 0][lrow] = a0.x; As[lcol + 1][lrow] = a0.y;
        As[lcol + 2][lrow] = a0.z; As[lcol + 3][lrow] = a0.w;
        As[lcol + 0][lrow + 64] = a1.x; As[lcol + 1][lrow + 64] = a1.y;
        As[lcol + 2][lrow + 64] = a1.z; As[lcol + 3][lrow + 64] = a1.w;
        Bs[lcol + 0][lrow] = b0.x; Bs[lcol + 1][lrow] = b0.y;
        Bs[lcol + 2][lrow] = b0.z; Bs[lcol + 3][lrow] = b0.w;
        Bs[lcol + 0][lrow + 64] = b1.x; Bs[lcol + 1][lrow + 64] = b1.y;
        Bs[lcol + 2][lrow + 64] = b1.z; Bs[lcol + 3][lrow + 64] = b1.w;
        __syncthreads();

#pragma unroll
        for (int k = 0; k < BK; k++) {
            float4 av0 = *(const float4*)&As[k][m0];
            float4 av1 = *(const float4*)&As[k][m0 + 4];
            float4 bv0 = *(const float4*)&Bs[k][n0];
            float4 bv1 = *(const float4*)&Bs[k][n0 + 4];
            u64 b2[4];
            b2[0] = packf2(bv0.x, bv0.y);
            b2[1] = packf2(bv0.z, bv0.w);
            b2[2] = packf2(bv1.x, bv1.y);
            b2[3] = packf2(bv1.z, bv1.w);
            float a[8] = {av0.x, av0.y, av0.z, av0.w, av1.x, av1.y, av1.z, av1.w};
#pragma unroll
            for (int i = 0; i < 8; i++) {
                u64 a2 = packf2(a[i], a[i]);
#pragma unroll
                for (int j = 0; j < 4; j++) acc[i][j] = ffma2(a2, b2[j], acc[i][j]);
            }
        }
    }

    // store (f32x2 pair = 8-byte aligned store; pairs never straddle N_TRAIN
    // since N_TRAIN is even and n is even)
#pragma unroll
    for (int i = 0; i < 8; i++) {
        float* orow = g_sim + (size_t)(m_base + m0 + i) * N_TRAIN;
#pragma unroll
        for (int j = 0; j < 4; j++) {
            int n = n_base + n0 + 2 * j;
            if (n < N_TRAIN) *(u64*)(orow + n) = acc[i][j];
        }
    }
}

// ---------------------------------------------------------------------------
// Per-row top-200 + softmax + cumulative class histograms. One block per row.
// ---------------------------------------------------------------------------
__device__ __forceinline__ u32 enc_key(float f) {
    u32 u = __float_as_uint(f);
    return (u & 0x80000000u) ? ~u : (u | 0x80000000u);
}
__device__ __forceinline__ float dec_key(u32 u) {
    return (u & 0x80000000u) ? __uint_as_float(u & 0x7FFFFFFFu)
                             : __uint_as_float(~u);
}

// descending bitonic sort of n (power of 2) u64 entries, 256 threads
__device__ void bitonic_desc(u64* a, int n, int tid) {
    for (int k = 2; k <= n; k <<= 1) {
        for (int j = k >> 1; j > 0; j >>= 1) {
            for (int i = tid; i < n; i += 256) {
                int ixj = i ^ j;
                if (ixj > i) {
                    u64 x = a[i], y = a[ixj];
                    bool desc = ((i & k) == 0);
                    if (desc ? (x < y) : (x > y)) { a[i] = y; a[ixj] = x; }
                }
            }
            __syncthreads();
        }
    }
}

__global__ __launch_bounds__(256) void select_kernel(
    const int* __restrict__ labels, float* __restrict__ out)
{
    __shared__ u64 buf[CAP];        // 32 KB: samples, then candidates
    __shared__ float hist[NCLS];
    __shared__ float tw[MAXK];
    __shared__ int   tl[MAXK];
    __shared__ float red[256];
    __shared__ u32 s_cnt;
    __shared__ u32 s_thr;

    const int tid = threadIdx.x;
    const int row = blockIdx.x;
    const float* sim = g_sim + (size_t)row * N_TRAIN;

    // --- 1) sample 4096 elements (stride 24), sort, threshold = rank-64 key.
    // Expected candidate count ~(64/4096)*100000 = 1562; P(<200) and P(>4096)
    // are both many sigma out.
    for (int i = tid; i < CAP; i += 256)
        buf[i] = ((u64)enc_key(sim[i * 24]) << 32);
    if (tid == 0) s_cnt = 0;
    __syncthreads();
    bitonic_desc(buf, CAP, tid);
    if (tid == 0) s_thr = (u32)(buf[63] >> 32);
    __syncthreads();
    const u32 thr = s_thr;

    // --- 2) collect all elements with key >= thr (vectorized scan)
    const float4* sim4 = (const float4*)sim;
    for (int i = tid; i < N_TRAIN / 4; i += 256) {
        float4 v = sim4[i];
        float c[4] = {v.x, v.y, v.z, v.w};
#pragma unroll
        for (int q = 0; q < 4; q++) {
            u32 key = enc_key(c[q]);
            if (key >= thr) {
                u32 p = atomicAdd(&s_cnt, 1u);
                // key desc, then index asc on ties (matches top_k tie-break)
                if (p < CAP) buf[p] = ((u64)key << 32) | (u32)(~(u32)(4 * i + q));
            }
        }
    }
    __syncthreads();
    int C = min((int)s_cnt, CAP);
    int np2 = 256;
    while (np2 < C) np2 <<= 1;
    for (int i = C + tid; i < np2; i += 256) buf[i] = 0ULL;
    __syncthreads();
    bitonic_desc(buf, np2, tid);

    // --- 3) softmax over the sorted top-200
    float smax = dec_key((u32)(buf[0] >> 32));
    float w = 0.0f;
    int lab = 0;
    if (tid < MAXK && tid < C) {
        u64 e = buf[tid];
        float s = dec_key((u32)(e >> 32));
        u32 idx = ~(u32)e;
        w = __expf((s - smax) * TINV);
        lab = labels[idx];
    }
    red[tid] = w;
    __syncthreads();
    for (int off = 128; off > 0; off >>= 1) {
        if (tid < off) red[tid] += red[tid + off];
        __syncthreads();
    }
    const float wsum = red[0];
    if (tid < MAXK) { tw[tid] = w / wsum; tl[tid] = lab; }

    // --- 4) cumulative class histograms for k = 10, 20, 100, 200
    for (int c = tid; c < NCLS; c += 256) hist[c] = 0.0f;
    __syncthreads();
    const int seg_lo[4] = {0, 10, 20, 100};
    const int seg_hi[4] = {10, 20, 100, 200};
    for (int ks = 0; ks < 4; ks++) {
        if (tid >= seg_lo[ks] && tid < seg_hi[ks])
            atomicAdd(&hist[tl[tid]], tw[tid]);
        __syncthreads();
        float* o = out + ((size_t)ks * B_ROWS + row) * NCLS;
        for (int c = tid; c < NCLS; c += 256) o[c] = hist[c];
        __syncthreads();
    }
}

// ---------------------------------------------------------------------------
extern "C" void kernel_launch(void* const* d_in, const int* in_sizes, int n_in,
                              void* d_out, int out_size)
{
    const float* feats  = (const float*)d_in[0];  // [2048, 1024]
    const float* train  = (const float*)d_in[1];  // [100000, 1024]
    const int*   labels = (const int*)d_in[2];    // [100000]
    float* out = (float*)d_out;                   // 4 x [2048, 1000]

    dim3 grid((N_TRAIN + BN - 1) / BN, B_ROWS / BM);
    gemm_kernel<<<grid, 256>>>(feats, train);
    select_kernel<<<B_ROWS, 256>>>(labels, out);
}